// round 7
// baseline (speedup 1.0000x reference)
#include <cuda_runtime.h>
#include <cuda_bf16.h>
#include <stdint.h>
#include <math.h>

// Problem constants
#define BATCH 2
#define SEQ   2048
#define EMB   1024
#define NHEAD 16
#define HDIM  64
#define MROWS (BATCH * SEQ)      // 4096
#define ATTN_SCALE 0.125f        // 1/sqrt(64)
#define NKS (EMB / 32)           // 32 k-steps

// ---------------------------------------------------------------------------
// Scratch (allocation-free rule: __device__ globals)
// ---------------------------------------------------------------------------
__device__ float g_Q[MROWS * EMB];
__device__ float g_K[MROWS * EMB];
__device__ float g_V[MROWS * EMB];
__device__ float g_A[MROWS * EMB];
__device__ float g_RX[MROWS * EMB];   // tf32-rounded activation input
__device__ float g_RW[EMB * EMB];     // tf32-rounded weight

// ---------------------------------------------------------------------------
// helpers
// ---------------------------------------------------------------------------
__device__ __forceinline__ uint32_t f2tf32(float x) {
    uint32_t u;
    asm("cvt.rna.tf32.f32 %0, %1;" : "=r"(u) : "f"(x));
    return u;
}
__device__ __forceinline__ float tf32r(float x) { return __uint_as_float(f2tf32(x)); }

__device__ __forceinline__ void mma8(float* c, const uint32_t* a, const uint32_t* b) {
    asm volatile(
        "mma.sync.aligned.m16n8k8.row.col.f32.tf32.tf32.f32 "
        "{%0,%1,%2,%3}, {%4,%5,%6,%7}, {%8,%9}, {%0,%1,%2,%3};"
        : "+f"(c[0]), "+f"(c[1]), "+f"(c[2]), "+f"(c[3])
        : "r"(a[0]), "r"(a[1]), "r"(a[2]), "r"(a[3]), "r"(b[0]), "r"(b[1]));
}

__device__ __forceinline__ void cpa16(uint32_t s, const void* g) {
    asm volatile("cp.async.cg.shared.global [%0], [%1], 16;\n" :: "r"(s), "l"(g));
}
#define CP_COMMIT() asm volatile("cp.async.commit_group;\n" ::: "memory")
#define CP_WAIT2()  asm volatile("cp.async.wait_group 2;\n"  ::: "memory")

__device__ __forceinline__ void ldsm4(uint32_t& r0, uint32_t& r1, uint32_t& r2,
                                      uint32_t& r3, uint32_t addr) {
    asm volatile("ldmatrix.sync.aligned.m8n8.x4.shared.b16 {%0,%1,%2,%3}, [%4];"
                 : "=r"(r0), "=r"(r1), "=r"(r2), "=r"(r3) : "r"(addr));
}

// ---------------------------------------------------------------------------
// tf32 rounding pre-pass (elementwise, vectorized)
// ---------------------------------------------------------------------------
__global__ void __launch_bounds__(256)
round_tf32_kernel(const float4* __restrict__ in, float4* __restrict__ out)
{
    int i = blockIdx.x * 256 + threadIdx.x;
    float4 v = in[i];
    v.x = tf32r(v.x); v.y = tf32r(v.y); v.z = tf32r(v.z); v.w = tf32r(v.w);
    out[i] = v;
}

// ---------------------------------------------------------------------------
// GEMM: C[4096,1024] = A @ W^T + bias. Inputs pre-rounded to tf32.
// CTA 128x128, k-step 32. 3-stage cp.async pipeline, SW128 swizzled SMEM,
// ldmatrix fragment loads (double-buffered across kt), mma.m16n8k8.tf32.
// ---------------------------------------------------------------------------
#define STAGE_BYTES 32768          // A tile 16KB + B tile 16KB
#define GEMM_SMEM   (3 * STAGE_BYTES)

__global__ void __launch_bounds__(256)
gemm_tf32_v3(const float* __restrict__ A, const float* __restrict__ Bw,
             const float* __restrict__ bias, float* __restrict__ C)
{
    extern __shared__ __align__(128) char dynsmem[];
    const uint32_t smemBase = (uint32_t)__cvta_generic_to_shared(dynsmem);

    const int tid  = threadIdx.x;
    const int lane = tid & 31;
    const int warp = tid >> 5;
    const int wm   = warp & 1;     // m offset wm*64
    const int wn   = warp >> 1;    // n offset wn*32
    const int rowBlk = blockIdx.y * 128;
    const int colBlk = blockIdx.x * 128;

    // per-thread cp.async chunk coords (4 chunks per tile per thread)
    int crow[4]; uint32_t csw[4];
#pragma unroll
    for (int i = 0; i < 4; i++) {
        int cid = tid + i * 256;        // 0..1023
        int r   = cid >> 3;
        int cc  = cid & 7;
        crow[i] = r;
        csw[i]  = r * 128 + ((cc ^ (r & 7)) << 4);
    }

    float acc[4][4][4];
#pragma unroll
    for (int mi = 0; mi < 4; mi++)
#pragma unroll
        for (int ni = 0; ni < 4; ni++)
#pragma unroll
            for (int q = 0; q < 4; q++) acc[mi][ni][q] = 0.f;

    const int aRowL = (lane & 15);
    const int aChL  = (lane >> 4);
    const int bRowL = ((lane >> 4) << 3) + (lane & 7);
    const int bChL  = ((lane >> 3) & 1);

    auto issue = [&](int ks, int stage) {
        uint32_t sA = smemBase + stage * STAGE_BYTES;
        uint32_t sB = sA + 16384;
        const float* Ag = A  + (size_t)rowBlk * EMB + ks * 32;
        const float* Bg = Bw + (size_t)colBlk * EMB + ks * 32;
#pragma unroll
        for (int i = 0; i < 4; i++) {
            int cc = (tid + i * 256) & 7;
            cpa16(sA + csw[i], Ag + (size_t)crow[i] * EMB + cc * 4);
            cpa16(sB + csw[i], Bg + (size_t)crow[i] * EMB + cc * 4);
        }
    };

    auto loadFrags = [&](uint32_t sA, uint32_t sB, int kt,
                         uint32_t af[4][4], uint32_t bf[4][2]) {
#pragma unroll
        for (int mt = 0; mt < 4; mt++) {
            int r  = wm * 64 + mt * 16 + aRowL;
            int ch = 2 * kt + aChL;
            uint32_t addr = sA + r * 128 + ((ch ^ (r & 7)) << 4);
            ldsm4(af[mt][0], af[mt][1], af[mt][2], af[mt][3], addr);
        }
#pragma unroll
        for (int p = 0; p < 2; p++) {
            int r  = wn * 32 + p * 16 + bRowL;
            int ch = 2 * kt + bChL;
            uint32_t addr = sB + r * 128 + ((ch ^ (r & 7)) << 4);
            uint32_t t0, t1, t2, t3;
            ldsm4(t0, t1, t2, t3, addr);
            bf[2 * p][0] = t0; bf[2 * p][1] = t1;
            bf[2 * p + 1][0] = t2; bf[2 * p + 1][1] = t3;
        }
    };

    issue(0, 0); CP_COMMIT();
    issue(1, 1); CP_COMMIT();

#pragma unroll 1
    for (int ks = 0; ks < NKS; ks++) {
        if (ks + 2 < NKS) issue(ks + 2, (ks + 2) % 3);
        CP_COMMIT();
        CP_WAIT2();
        __syncthreads();

        uint32_t sA = smemBase + (ks % 3) * STAGE_BYTES;
        uint32_t sB = sA + 16384;

        uint32_t afb[2][4][4];
        uint32_t bfb[2][4][2];
        loadFrags(sA, sB, 0, afb[0], bfb[0]);

#pragma unroll
        for (int kt = 0; kt < 4; kt++) {
            int cur = kt & 1;
            if (kt < 3) loadFrags(sA, sB, kt + 1, afb[cur ^ 1], bfb[cur ^ 1]);
#pragma unroll
            for (int mi = 0; mi < 4; mi++)
#pragma unroll
                for (int ni = 0; ni < 4; ni++)
                    mma8(acc[mi][ni], afb[cur][mi], bfb[cur][ni]);
        }
        __syncthreads();
    }

    // ---- epilogue: bias + store ----
    const int g  = lane >> 2;
    const int tg = lane & 3;
#pragma unroll
    for (int mi = 0; mi < 4; mi++) {
        int r0 = rowBlk + wm * 64 + mi * 16 + g;
#pragma unroll
        for (int ni = 0; ni < 4; ni++) {
            int c0 = colBlk + wn * 32 + ni * 8 + tg * 2;
            float2 bb = *(const float2*)&bias[c0];
            float2 s0 = make_float2(acc[mi][ni][0] + bb.x, acc[mi][ni][1] + bb.y);
            float2 s1 = make_float2(acc[mi][ni][2] + bb.x, acc[mi][ni][3] + bb.y);
            *(float2*)&C[(size_t)r0 * EMB + c0]       = s0;
            *(float2*)&C[(size_t)(r0 + 8) * EMB + c0] = s1;
        }
    }
}

// ---------------------------------------------------------------------------
// Causal flash attention, split-D: 2 threads per query, each owns 32 of the
// 64 head dims. Scores combined via one shfl.bfly per key. Halves register
// pressure (occupancy was the measured limiter: occ=10.8%, issue=45.9%).
// Block: 128 threads = 64 queries. Grid: (SEQ/64, BATCH*NHEAD).
// ---------------------------------------------------------------------------
__global__ void __launch_bounds__(128)
attn_kernel(const float* __restrict__ Q, const float* __restrict__ K,
            const float* __restrict__ V, float* __restrict__ O)
{
    __shared__ __align__(16) float Ks[64][64];
    __shared__ __align__(16) float Vs[64][64];

    const int bh = blockIdx.y;
    const int b  = bh >> 4;
    const int h  = bh & 15;
    const int qi   = blockIdx.x * 64 + (threadIdx.x >> 1);  // this thread's query
    const int half = threadIdx.x & 1;                       // dim half [half*32, +32)

    const float* qptr = Q + ((size_t)(b * SEQ + qi)) * EMB + h * HDIM + half * 32;
    float4 q4[8];
#pragma unroll
    for (int i = 0; i < 8; i++) q4[i] = ((const float4*)qptr)[i];

    float4 o4[8];
#pragma unroll
    for (int i = 0; i < 8; i++) o4[i] = make_float4(0.f, 0.f, 0.f, 0.f);

    float m = -1e30f, l = 0.f;

    const float* Kbase = K + ((size_t)b * SEQ) * EMB + h * HDIM;
    const float* Vbase = V + ((size_t)b * SEQ) * EMB + h * HDIM;

    const int nTiles = blockIdx.x + 1;   // 64-key tiles covering keys <= last query

    for (int t = 0; t < nTiles; t++) {
        const int base = t * 64;
        __syncthreads();
        for (int f = threadIdx.x; f < 64 * 16; f += 128) {
            int r = f >> 4;
            int c = f & 15;
            ((float4*)Ks[r])[c] = ((const float4*)(Kbase + (size_t)(base + r) * EMB))[c];
            ((float4*)Vs[r])[c] = ((const float4*)(Vbase + (size_t)(base + r) * EMB))[c];
        }
        __syncthreads();

#pragma unroll 1
        for (int sc = 0; sc < 4; sc++) {
            const int j0 = base + sc * 16;
            if (j0 > qi) break;   // fully masked for this query

            float s[16];
#pragma unroll
            for (int j = 0; j < 16; j++) {
                const float4* kr = (const float4*)(&Ks[sc * 16 + j][half * 32]);
                float acc0 = 0.f, acc1 = 0.f;
#pragma unroll
                for (int d = 0; d < 8; d += 2) {
                    float4 k0v = kr[d + 0];
                    float4 k1v = kr[d + 1];
                    acc0 += q4[d+0].x*k0v.x + q4[d+0].y*k0v.y + q4[d+0].z*k0v.z + q4[d+0].w*k0v.w;
                    acc1 += q4[d+1].x*k1v.x + q4[d+1].y*k1v.y + q4[d+1].z*k1v.z + q4[d+1].w*k1v.w;
                }
                s[j] = acc0 + acc1;
            }
            // combine halves: partner lane holds the other 32 dims
#pragma unroll
            for (int j = 0; j < 16; j++) {
                float sv = (s[j] + __shfl_xor_sync(0xFFFFFFFFu, s[j], 1)) * ATTN_SCALE;
                s[j] = (j0 + j > qi) ? -1e30f : sv;
            }

            float cmax = s[0];
#pragma unroll
            for (int j = 1; j < 16; j++) cmax = fmaxf(cmax, s[j]);
            float mn   = fmaxf(m, cmax);
            float corr = __expf(m - mn);
            l *= corr;
#pragma unroll
            for (int i = 0; i < 8; i++) {
                o4[i].x *= corr; o4[i].y *= corr; o4[i].z *= corr; o4[i].w *= corr;
            }
            m = mn;

#pragma unroll
            for (int j = 0; j < 16; j++) {
                float p = __expf(s[j] - mn);
                l += p;
                const float4* vr = (const float4*)(&Vs[sc * 16 + j][half * 32]);
#pragma unroll
                for (int d = 0; d < 8; d++) {
                    float4 vv = vr[d];
                    o4[d].x += p * vv.x;
                    o4[d].y += p * vv.y;
                    o4[d].z += p * vv.z;
                    o4[d].w += p * vv.w;
                }
            }
        }
    }

    const float inv = 1.f / l;
    float* optr = O + ((size_t)(b * SEQ + qi)) * EMB + h * HDIM + half * 32;
#pragma unroll
    for (int i = 0; i < 8; i++) {
        float4 st;
        st.x = tf32r(o4[i].x * inv); st.y = tf32r(o4[i].y * inv);
        st.z = tf32r(o4[i].z * inv); st.w = tf32r(o4[i].w * inv);
        ((float4*)optr)[i] = st;
    }
}

// ---------------------------------------------------------------------------
// Launch
// ---------------------------------------------------------------------------
extern "C" void kernel_launch(void* const* d_in, const int* in_sizes, int n_in,
                              void* d_out, int out_size)
{
    const float* xq = (const float*)d_in[0];
    const float* xk = (const float*)d_in[1];
    const float* xv = (const float*)d_in[2];
    // d_in[3] = mask (deterministic causal tril) — exploited structurally
    const float* Wq = (const float*)d_in[4];
    const float* bq = (const float*)d_in[5];
    const float* Wk = (const float*)d_in[6];
    const float* bk = (const float*)d_in[7];
    const float* Wv = (const float*)d_in[8];
    const float* bv = (const float*)d_in[9];
    const float* Wo = (const float*)d_in[10];
    const float* bo = (const float*)d_in[11];
    float* out = (float*)d_out;

    float *pQ, *pK, *pV, *pA, *pRX, *pRW;
    cudaGetSymbolAddress((void**)&pQ,  g_Q);
    cudaGetSymbolAddress((void**)&pK,  g_K);
    cudaGetSymbolAddress((void**)&pV,  g_V);
    cudaGetSymbolAddress((void**)&pA,  g_A);
    cudaGetSymbolAddress((void**)&pRX, g_RX);
    cudaGetSymbolAddress((void**)&pRW, g_RW);

    cudaFuncSetAttribute(gemm_tf32_v3,
                         cudaFuncAttributeMaxDynamicSharedMemorySize, GEMM_SMEM);

    dim3 ggrid(EMB / 128, MROWS / 128);   // (8, 32)
    const int rX = (MROWS * EMB / 4) / 256;
    const int rW = (EMB * EMB / 4) / 256;

    // Q projection
    round_tf32_kernel<<<rX, 256>>>((const float4*)xq, (float4*)pRX);
    round_tf32_kernel<<<rW, 256>>>((const float4*)Wq, (float4*)pRW);
    gemm_tf32_v3<<<ggrid, 256, GEMM_SMEM>>>(pRX, pRW, bq, pQ);
    // K projection
    round_tf32_kernel<<<rX, 256>>>((const float4*)xk, (float4*)pRX);
    round_tf32_kernel<<<rW, 256>>>((const float4*)Wk, (float4*)pRW);
    gemm_tf32_v3<<<ggrid, 256, GEMM_SMEM>>>(pRX, pRW, bk, pK);
    // V projection
    round_tf32_kernel<<<rX, 256>>>((const float4*)xv, (float4*)pRX);
    round_tf32_kernel<<<rW, 256>>>((const float4*)Wv, (float4*)pRW);
    gemm_tf32_v3<<<ggrid, 256, GEMM_SMEM>>>(pRX, pRW, bv, pV);

    // attention (writes tf32-rounded output)
    dim3 agrid(SEQ / 64, BATCH * NHEAD); // (32, 32)
    attn_kernel<<<agrid, 128>>>(pQ, pK, pV, pA);

    // O projection
    round_tf32_kernel<<<rW, 256>>>((const float4*)Wo, (float4*)pRW);
    gemm_tf32_v3<<<ggrid, 256, GEMM_SMEM>>>(pA, pRW, bo, out);
}

// round 8
// speedup vs baseline: 3.7450x; 3.7450x over previous
#include <cuda_runtime.h>
#include <cuda_bf16.h>
#include <stdint.h>
#include <math.h>

// Problem constants
#define BATCH 2
#define SEQ   2048
#define EMB   1024
#define NHEAD 16
#define HDIM  64
#define MROWS (BATCH * SEQ)      // 4096
#define ATTN_SCALE 0.125f        // 1/sqrt(64)
#define NKS (EMB / 32)           // 32 k-steps

// ---------------------------------------------------------------------------
// Scratch (allocation-free rule: __device__ globals)
// ---------------------------------------------------------------------------
__device__ float g_Q[MROWS * EMB];
__device__ float g_K[MROWS * EMB];
__device__ float g_V[MROWS * EMB];
__device__ float g_A[MROWS * EMB];
__device__ float g_VT[MROWS * EMB];   // V transposed: [b*EMB + d][s]
__device__ float g_RX[MROWS * EMB];   // tf32-rounded activation input
__device__ float g_RW[EMB * EMB];     // tf32-rounded weight

// ---------------------------------------------------------------------------
// helpers
// ---------------------------------------------------------------------------
__device__ __forceinline__ uint32_t f2tf32(float x) {
    uint32_t u;
    asm("cvt.rna.tf32.f32 %0, %1;" : "=r"(u) : "f"(x));
    return u;
}
__device__ __forceinline__ float tf32r(float x) { return __uint_as_float(f2tf32(x)); }

__device__ __forceinline__ void mma8(float* c, const uint32_t* a, const uint32_t* b) {
    asm volatile(
        "mma.sync.aligned.m16n8k8.row.col.f32.tf32.tf32.f32 "
        "{%0,%1,%2,%3}, {%4,%5,%6,%7}, {%8,%9}, {%0,%1,%2,%3};"
        : "+f"(c[0]), "+f"(c[1]), "+f"(c[2]), "+f"(c[3])
        : "r"(a[0]), "r"(a[1]), "r"(a[2]), "r"(a[3]), "r"(b[0]), "r"(b[1]));
}

__device__ __forceinline__ void cpa16(uint32_t s, const void* g) {
    asm volatile("cp.async.cg.shared.global [%0], [%1], 16;\n" :: "r"(s), "l"(g));
}
#define CP_COMMIT() asm volatile("cp.async.commit_group;\n" ::: "memory")
#define CP_WAIT0()  asm volatile("cp.async.wait_group 0;\n"  ::: "memory")
#define CP_WAIT1()  asm volatile("cp.async.wait_group 1;\n"  ::: "memory")
#define CP_WAIT2()  asm volatile("cp.async.wait_group 2;\n"  ::: "memory")

__device__ __forceinline__ void ldsm4(uint32_t& r0, uint32_t& r1, uint32_t& r2,
                                      uint32_t& r3, uint32_t addr) {
    asm volatile("ldmatrix.sync.aligned.m8n8.x4.shared.b16 {%0,%1,%2,%3}, [%4];"
                 : "=r"(r0), "=r"(r1), "=r"(r2), "=r"(r3) : "r"(addr));
}

// 64x64 fp32 tile, 256B rows, SW128 per 128B atom:
// 16B chunk c (0..15) of row r at r*256 + (c>>3)*128 + (((c&7)^(r&7))<<4)
__device__ __forceinline__ uint32_t tadr(int r, int c) {
    return (uint32_t)(r * 256 + ((c >> 3) << 7) + ((((c & 7) ^ (r & 7))) << 4));
}

// ---------------------------------------------------------------------------
// tf32 rounding pre-pass (elementwise, vectorized)
// ---------------------------------------------------------------------------
__global__ void __launch_bounds__(256)
round_tf32_kernel(const float4* __restrict__ in, float4* __restrict__ out)
{
    int i = blockIdx.x * 256 + threadIdx.x;
    float4 v = in[i];
    v.x = tf32r(v.x); v.y = tf32r(v.y); v.z = tf32r(v.z); v.w = tf32r(v.w);
    out[i] = v;
}

// ---------------------------------------------------------------------------
// V transpose: g_V [b*SEQ+s][e] -> g_VT [b*EMB+e][s]   (tiled 32x32)
// ---------------------------------------------------------------------------
__global__ void __launch_bounds__(256)
transpose_v(const float* __restrict__ V, float* __restrict__ VT)
{
    __shared__ float ts[32][33];
    const int s0 = blockIdx.x * 32;
    const int d0 = blockIdx.y * 32;
    const int b  = blockIdx.z;
    const int tx = threadIdx.x & 31;
    const int ty = threadIdx.x >> 5;   // 0..7
#pragma unroll
    for (int i = ty; i < 32; i += 8)
        ts[i][tx] = V[(size_t)(b * SEQ + s0 + i) * EMB + d0 + tx];
    __syncthreads();
#pragma unroll
    for (int i = ty; i < 32; i += 8)
        VT[(size_t)(b * EMB + d0 + i) * SEQ + s0 + tx] = ts[tx][i];
}

// ---------------------------------------------------------------------------
// GEMM (R4-proven): C[4096,1024] = A @ W^T + bias. Inputs pre-rounded tf32.
// roundOut != 0 -> outputs rounded to tf32 (for Q/K/V feeding mma attention).
// ---------------------------------------------------------------------------
#define STAGE_BYTES 32768
#define GEMM_SMEM   (3 * STAGE_BYTES)

__global__ void __launch_bounds__(256)
gemm_tf32_v3(const float* __restrict__ A, const float* __restrict__ Bw,
             const float* __restrict__ bias, float* __restrict__ C, int roundOut)
{
    extern __shared__ __align__(128) char dynsmem[];
    const uint32_t smemBase = (uint32_t)__cvta_generic_to_shared(dynsmem);

    const int tid  = threadIdx.x;
    const int lane = tid & 31;
    const int warp = tid >> 5;
    const int wm   = warp & 1;
    const int wn   = warp >> 1;
    const int rowBlk = blockIdx.y * 128;
    const int colBlk = blockIdx.x * 128;

    int crow[4]; uint32_t csw[4];
#pragma unroll
    for (int i = 0; i < 4; i++) {
        int cid = tid + i * 256;
        int r   = cid >> 3;
        int cc  = cid & 7;
        crow[i] = r;
        csw[i]  = r * 128 + ((cc ^ (r & 7)) << 4);
    }

    float acc[4][4][4];
#pragma unroll
    for (int mi = 0; mi < 4; mi++)
#pragma unroll
        for (int ni = 0; ni < 4; ni++)
#pragma unroll
            for (int q = 0; q < 4; q++) acc[mi][ni][q] = 0.f;

    const int aRowL = (lane & 15);
    const int aChL  = (lane >> 4);
    const int bRowL = ((lane >> 4) << 3) + (lane & 7);
    const int bChL  = ((lane >> 3) & 1);

    auto issue = [&](int ks, int stage) {
        uint32_t sA = smemBase + stage * STAGE_BYTES;
        uint32_t sB = sA + 16384;
        const float* Ag = A  + (size_t)rowBlk * EMB + ks * 32;
        const float* Bg = Bw + (size_t)colBlk * EMB + ks * 32;
#pragma unroll
        for (int i = 0; i < 4; i++) {
            int cc = (tid + i * 256) & 7;
            cpa16(sA + csw[i], Ag + (size_t)crow[i] * EMB + cc * 4);
            cpa16(sB + csw[i], Bg + (size_t)crow[i] * EMB + cc * 4);
        }
    };

    issue(0, 0); CP_COMMIT();
    issue(1, 1); CP_COMMIT();

#pragma unroll 1
    for (int ks = 0; ks < NKS; ks++) {
        if (ks + 2 < NKS) issue(ks + 2, (ks + 2) % 3);
        CP_COMMIT();
        CP_WAIT2();
        __syncthreads();

        uint32_t sA = smemBase + (ks % 3) * STAGE_BYTES;
        uint32_t sB = sA + 16384;

#pragma unroll
        for (int kt = 0; kt < 4; kt++) {
            uint32_t af[4][4];
            uint32_t bf[4][2];
#pragma unroll
            for (int mt = 0; mt < 4; mt++) {
                int r  = wm * 64 + mt * 16 + aRowL;
                int ch = 2 * kt + aChL;
                uint32_t addr = sA + r * 128 + ((ch ^ (r & 7)) << 4);
                ldsm4(af[mt][0], af[mt][1], af[mt][2], af[mt][3], addr);
            }
#pragma unroll
            for (int p = 0; p < 2; p++) {
                int r  = wn * 32 + p * 16 + bRowL;
                int ch = 2 * kt + bChL;
                uint32_t addr = sB + r * 128 + ((ch ^ (r & 7)) << 4);
                uint32_t t0, t1, t2, t3;
                ldsm4(t0, t1, t2, t3, addr);
                bf[2 * p][0] = t0; bf[2 * p][1] = t1;
                bf[2 * p + 1][0] = t2; bf[2 * p + 1][1] = t3;
            }
#pragma unroll
            for (int mi = 0; mi < 4; mi++)
#pragma unroll
                for (int ni = 0; ni < 4; ni++)
                    mma8(acc[mi][ni], af[mi], bf[ni]);
        }
        __syncthreads();
    }

    const int g  = lane >> 2;
    const int tg = lane & 3;
#pragma unroll
    for (int mi = 0; mi < 4; mi++) {
        int r0 = rowBlk + wm * 64 + mi * 16 + g;
#pragma unroll
        for (int ni = 0; ni < 4; ni++) {
            int c0 = colBlk + wn * 32 + ni * 8 + tg * 2;
            float2 bb = *(const float2*)&bias[c0];
            float2 s0 = make_float2(acc[mi][ni][0] + bb.x, acc[mi][ni][1] + bb.y);
            float2 s1 = make_float2(acc[mi][ni][2] + bb.x, acc[mi][ni][3] + bb.y);
            if (roundOut) {
                s0.x = tf32r(s0.x); s0.y = tf32r(s0.y);
                s1.x = tf32r(s1.x); s1.y = tf32r(s1.y);
            }
            *(float2*)&C[(size_t)r0 * EMB + c0]       = s0;
            *(float2*)&C[(size_t)(r0 + 8) * EMB + c0] = s1;
        }
    }
}

// ---------------------------------------------------------------------------
// MMA flash attention. CTA = 64 queries of one (b,h). 4 warps x m16 rows.
// S = Q@K^T via mma (K tiles in SMEM, B-layout native), online softmax in
// c-fragments, P -> SMEM -> ldsm (layout conversion), O += P@V via mma with
// pre-transposed V (g_VT rows = dims). Double-buffered K/VT cp.async tiles.
// SMEM: P 16K | K0 16K | K1 16K | V0 16K | V1 16K = 80KB.
// ---------------------------------------------------------------------------
#define ATT_SMEM (5 * 16384)

__global__ void __launch_bounds__(128)
attn_mma_kernel(const float* __restrict__ Q, const float* __restrict__ K,
                const float* __restrict__ VT, float* __restrict__ O)
{
    extern __shared__ __align__(128) char asmem[];
    const uint32_t base = (uint32_t)__cvta_generic_to_shared(asmem);
    const uint32_t Pb = base;

    const int tid  = threadIdx.x;
    const int lane = tid & 31;
    const int warp = tid >> 5;
    const int bh = blockIdx.y;
    const int b  = bh >> 4;
    const int h  = bh & 15;
    const int qBase = blockIdx.x * 64;
    const int nT = blockIdx.x + 1;

    const int g  = lane >> 2;      // row-in-16 group
    const int tg = lane & 3;
    const int aRowL = lane & 15;
    const int aChL  = lane >> 4;
    const int bRowL = ((lane >> 4) << 3) + (lane & 7);
    const int bChL  = ((lane >> 3) & 1);

    // ---- stage Q tile into P region, preload A-fragments ----
    {
        const float* Qg = Q + ((size_t)(b * SEQ + qBase)) * EMB + h * HDIM;
#pragma unroll
        for (int i = 0; i < 8; i++) {
            int f = tid + i * 128;
            int r = f >> 4, c = f & 15;
            cpa16(Pb + tadr(r, c), Qg + (size_t)r * EMB + c * 4);
        }
    }
    CP_COMMIT(); CP_WAIT0();
    __syncthreads();

    uint32_t qf[8][4];
#pragma unroll
    for (int kt = 0; kt < 8; kt++) {
        int r = warp * 16 + aRowL;
        ldsm4(qf[kt][0], qf[kt][1], qf[kt][2], qf[kt][3],
              Pb + tadr(r, 2 * kt + aChL));
    }
    __syncthreads();   // P region reusable now

    float oacc[8][4];
#pragma unroll
    for (int n = 0; n < 8; n++)
#pragma unroll
        for (int q = 0; q < 4; q++) oacc[n][q] = 0.f;
    float m0 = -1e30f, m1 = -1e30f, l0 = 0.f, l1 = 0.f;

    auto prefetch = [&](int t) {
        uint32_t Kb = base + 16384 + (t & 1) * 16384;
        uint32_t Vb = base + 49152 + (t & 1) * 16384;
        const float* Kg = K  + ((size_t)(b * SEQ + t * 64)) * EMB + h * HDIM;
        const float* Vg = VT + ((size_t)(b * EMB + h * HDIM)) * SEQ + t * 64;
#pragma unroll
        for (int i = 0; i < 8; i++) {
            int f = tid + i * 128;
            int r = f >> 4, c = f & 15;
            cpa16(Kb + tadr(r, c), Kg + (size_t)r * EMB + c * 4);
            cpa16(Vb + tadr(r, c), Vg + (size_t)r * SEQ + c * 4);
        }
    };

    prefetch(0); CP_COMMIT();
    if (nT > 1) prefetch(1);
    CP_COMMIT();

#pragma unroll 1
    for (int t = 0; t < nT; t++) {
        CP_WAIT1();
        __syncthreads();

        const uint32_t Kb = base + 16384 + (t & 1) * 16384;
        const uint32_t Vb = base + 49152 + (t & 1) * 16384;

        // ---- S = Q @ K^T ----
        float sacc[8][4];
#pragma unroll
        for (int n = 0; n < 8; n++)
#pragma unroll
            for (int q = 0; q < 4; q++) sacc[n][q] = 0.f;

#pragma unroll
        for (int kt = 0; kt < 8; kt++) {
            uint32_t bf[8][2];
#pragma unroll
            for (int p = 0; p < 4; p++) {
                int r = p * 16 + bRowL;
                uint32_t t0, t1, t2, t3;
                ldsm4(t0, t1, t2, t3, Kb + tadr(r, 2 * kt + bChL));
                bf[2 * p][0] = t0;     bf[2 * p][1] = t1;
                bf[2 * p + 1][0] = t2; bf[2 * p + 1][1] = t3;
            }
#pragma unroll
            for (int n = 0; n < 8; n++)
                mma8(sacc[n], qf[kt], bf[n]);
        }

        // ---- scale + causal mask (diagonal tile only) ----
#pragma unroll
        for (int n = 0; n < 8; n++)
#pragma unroll
            for (int q = 0; q < 4; q++) sacc[n][q] *= ATTN_SCALE;

        if (t == blockIdx.x) {
            int r0 = warp * 16 + g;
            int r1 = r0 + 8;
#pragma unroll
            for (int n = 0; n < 8; n++) {
                int c0 = n * 8 + tg * 2;
                int c1 = c0 + 1;
                if (c0 > r0) sacc[n][0] = -1e30f;
                if (c1 > r0) sacc[n][1] = -1e30f;
                if (c0 > r1) sacc[n][2] = -1e30f;
                if (c1 > r1) sacc[n][3] = -1e30f;
            }
        }

        // ---- online softmax over c-fragments ----
        float tm0 = -1e30f, tm1 = -1e30f;
#pragma unroll
        for (int n = 0; n < 8; n++) {
            tm0 = fmaxf(tm0, fmaxf(sacc[n][0], sacc[n][1]));
            tm1 = fmaxf(tm1, fmaxf(sacc[n][2], sacc[n][3]));
        }
        tm0 = fmaxf(tm0, __shfl_xor_sync(0xFFFFFFFFu, tm0, 1));
        tm0 = fmaxf(tm0, __shfl_xor_sync(0xFFFFFFFFu, tm0, 2));
        tm1 = fmaxf(tm1, __shfl_xor_sync(0xFFFFFFFFu, tm1, 1));
        tm1 = fmaxf(tm1, __shfl_xor_sync(0xFFFFFFFFu, tm1, 2));

        float nm0 = fmaxf(m0, tm0);
        float nm1 = fmaxf(m1, tm1);
        float cr0 = __expf(m0 - nm0);
        float cr1 = __expf(m1 - nm1);
        m0 = nm0; m1 = nm1;

        float rs0 = 0.f, rs1 = 0.f;
#pragma unroll
        for (int n = 0; n < 8; n++) {
            float p0 = tf32r(__expf(sacc[n][0] - nm0));
            float p1 = tf32r(__expf(sacc[n][1] - nm0));
            float p2 = tf32r(__expf(sacc[n][2] - nm1));
            float p3 = tf32r(__expf(sacc[n][3] - nm1));
            sacc[n][0] = p0; sacc[n][1] = p1; sacc[n][2] = p2; sacc[n][3] = p3;
            rs0 += p0 + p1; rs1 += p2 + p3;
        }
        rs0 += __shfl_xor_sync(0xFFFFFFFFu, rs0, 1);
        rs0 += __shfl_xor_sync(0xFFFFFFFFu, rs0, 2);
        rs1 += __shfl_xor_sync(0xFFFFFFFFu, rs1, 1);
        rs1 += __shfl_xor_sync(0xFFFFFFFFu, rs1, 2);
        l0 = l0 * cr0 + rs0;
        l1 = l1 * cr1 + rs1;

#pragma unroll
        for (int n = 0; n < 8; n++) {
            oacc[n][0] *= cr0; oacc[n][1] *= cr0;
            oacc[n][2] *= cr1; oacc[n][3] *= cr1;
        }

        // ---- P -> SMEM (warp-private rows), layout conversion ----
        {
            int r0 = warp * 16 + g;
#pragma unroll
            for (int n = 0; n < 8; n++) {
                int off = n * 8 + tg * 2;          // col within 64
                int ch  = off >> 2;                // 16B chunk
                int byo = (off & 3) * 4;           // byte offset in chunk
                *(float2*)(asmem + tadr(r0, ch) + byo)     = make_float2(sacc[n][0], sacc[n][1]);
                *(float2*)(asmem + tadr(r0 + 8, ch) + byo) = make_float2(sacc[n][2], sacc[n][3]);
            }
        }
        __syncwarp();

        // ---- O += P @ V ----
#pragma unroll
        for (int kt = 0; kt < 8; kt++) {
            uint32_t pa[4];
            {
                int r = warp * 16 + aRowL;
                ldsm4(pa[0], pa[1], pa[2], pa[3], Pb + tadr(r, 2 * kt + aChL));
            }
            uint32_t vf[8][2];
#pragma unroll
            for (int p = 0; p < 4; p++) {
                int r = p * 16 + bRowL;
                uint32_t t0, t1, t2, t3;
                ldsm4(t0, t1, t2, t3, Vb + tadr(r, 2 * kt + bChL));
                vf[2 * p][0] = t0;     vf[2 * p][1] = t1;
                vf[2 * p + 1][0] = t2; vf[2 * p + 1][1] = t3;
            }
#pragma unroll
            for (int n = 0; n < 8; n++)
                mma8(oacc[n], pa, vf[n]);
        }

        __syncthreads();
        if (t + 2 < nT) prefetch(t + 2);
        CP_COMMIT();
    }

    // ---- epilogue: normalize, tf32-round (feeds O projection), store ----
    const float iv0 = 1.f / l0;
    const float iv1 = 1.f / l1;
    const int row0 = qBase + warp * 16 + g;
    const int row1 = row0 + 8;
    float* O0 = O + ((size_t)(b * SEQ + row0)) * EMB + h * HDIM;
    float* O1 = O + ((size_t)(b * SEQ + row1)) * EMB + h * HDIM;
#pragma unroll
    for (int n = 0; n < 8; n++) {
        int c = n * 8 + tg * 2;
        *(float2*)&O0[c] = make_float2(tf32r(oacc[n][0] * iv0), tf32r(oacc[n][1] * iv0));
        *(float2*)&O1[c] = make_float2(tf32r(oacc[n][2] * iv1), tf32r(oacc[n][3] * iv1));
    }
}

// ---------------------------------------------------------------------------
// Launch
// ---------------------------------------------------------------------------
extern "C" void kernel_launch(void* const* d_in, const int* in_sizes, int n_in,
                              void* d_out, int out_size)
{
    const float* xq = (const float*)d_in[0];
    const float* xk = (const float*)d_in[1];
    const float* xv = (const float*)d_in[2];
    // d_in[3] = mask (deterministic causal tril) — exploited structurally
    const float* Wq = (const float*)d_in[4];
    const float* bq = (const float*)d_in[5];
    const float* Wk = (const float*)d_in[6];
    const float* bk = (const float*)d_in[7];
    const float* Wv = (const float*)d_in[8];
    const float* bv = (const float*)d_in[9];
    const float* Wo = (const float*)d_in[10];
    const float* bo = (const float*)d_in[11];
    float* out = (float*)d_out;

    float *pQ, *pK, *pV, *pA, *pVT, *pRX, *pRW;
    cudaGetSymbolAddress((void**)&pQ,  g_Q);
    cudaGetSymbolAddress((void**)&pK,  g_K);
    cudaGetSymbolAddress((void**)&pV,  g_V);
    cudaGetSymbolAddress((void**)&pA,  g_A);
    cudaGetSymbolAddress((void**)&pVT, g_VT);
    cudaGetSymbolAddress((void**)&pRX, g_RX);
    cudaGetSymbolAddress((void**)&pRW, g_RW);

    cudaFuncSetAttribute(gemm_tf32_v3,
                         cudaFuncAttributeMaxDynamicSharedMemorySize, GEMM_SMEM);
    cudaFuncSetAttribute(attn_mma_kernel,
                         cudaFuncAttributeMaxDynamicSharedMemorySize, ATT_SMEM);

    dim3 ggrid(EMB / 128, MROWS / 128);   // (8, 32)
    const int rX = (MROWS * EMB / 4) / 256;
    const int rW = (EMB * EMB / 4) / 256;

    // Q projection (tf32-rounded output for mma attention)
    round_tf32_kernel<<<rX, 256>>>((const float4*)xq, (float4*)pRX);
    round_tf32_kernel<<<rW, 256>>>((const float4*)Wq, (float4*)pRW);
    gemm_tf32_v3<<<ggrid, 256, GEMM_SMEM>>>(pRX, pRW, bq, pQ, 1);
    // K projection
    round_tf32_kernel<<<rX, 256>>>((const float4*)xk, (float4*)pRX);
    round_tf32_kernel<<<rW, 256>>>((const float4*)Wk, (float4*)pRW);
    gemm_tf32_v3<<<ggrid, 256, GEMM_SMEM>>>(pRX, pRW, bk, pK, 1);
    // V projection
    round_tf32_kernel<<<rX, 256>>>((const float4*)xv, (float4*)pRX);
    round_tf32_kernel<<<rW, 256>>>((const float4*)Wv, (float4*)pRW);
    gemm_tf32_v3<<<ggrid, 256, GEMM_SMEM>>>(pRX, pRW, bv, pV, 1);

    // V transpose for mma attention B-operand
    transpose_v<<<dim3(SEQ / 32, EMB / 32, BATCH), 256>>>(pV, pVT);

    // MMA flash attention (writes tf32-rounded output)
    attn_mma_kernel<<<dim3(SEQ / 64, BATCH * NHEAD), 128, ATT_SMEM>>>(pQ, pK, pVT, pA);

    // O projection (full fp32 output)
    round_tf32_kernel<<<rW, 256>>>((const float4*)Wo, (float4*)pRW);
    gemm_tf32_v3<<<ggrid, 256, GEMM_SMEM>>>(pA, pRW, bo, out, 0);
}

// round 9
// speedup vs baseline: 3.9182x; 1.0463x over previous
#include <cuda_runtime.h>
#include <cuda_bf16.h>
#include <stdint.h>
#include <math.h>

// Problem constants
#define BATCH 2
#define SEQ   2048
#define EMB   1024
#define NHEAD 16
#define HDIM  64
#define MROWS (BATCH * SEQ)      // 4096
#define ATTN_SCALE 0.125f        // 1/sqrt(64)
#define NKS (EMB / 32)           // 32 k-steps

// ---------------------------------------------------------------------------
// Scratch (allocation-free rule: __device__ globals)
// ---------------------------------------------------------------------------
__device__ float g_Q[MROWS * EMB];
__device__ float g_K[MROWS * EMB];
__device__ float g_V[MROWS * EMB];
__device__ float g_A[MROWS * EMB];
__device__ float g_VT[MROWS * EMB];      // V transposed: [b*EMB + d][s]
__device__ float g_RX0[MROWS * EMB];     // tf32-rounded xq
__device__ float g_RX1[MROWS * EMB];     // tf32-rounded xk
__device__ float g_RX2[MROWS * EMB];     // tf32-rounded xv
__device__ float g_RW0[EMB * EMB];       // tf32-rounded Wq
__device__ float g_RW1[EMB * EMB];       // tf32-rounded Wk
__device__ float g_RW2[EMB * EMB];       // tf32-rounded Wv
__device__ float g_RW3[EMB * EMB];       // tf32-rounded Wo

// ---------------------------------------------------------------------------
// helpers
// ---------------------------------------------------------------------------
__device__ __forceinline__ uint32_t f2tf32(float x) {
    uint32_t u;
    asm("cvt.rna.tf32.f32 %0, %1;" : "=r"(u) : "f"(x));
    return u;
}
__device__ __forceinline__ float tf32r(float x) { return __uint_as_float(f2tf32(x)); }

__device__ __forceinline__ void mma8(float* c, const uint32_t* a, const uint32_t* b) {
    asm volatile(
        "mma.sync.aligned.m16n8k8.row.col.f32.tf32.tf32.f32 "
        "{%0,%1,%2,%3}, {%4,%5,%6,%7}, {%8,%9}, {%0,%1,%2,%3};"
        : "+f"(c[0]), "+f"(c[1]), "+f"(c[2]), "+f"(c[3])
        : "r"(a[0]), "r"(a[1]), "r"(a[2]), "r"(a[3]), "r"(b[0]), "r"(b[1]));
}

__device__ __forceinline__ void cpa16(uint32_t s, const void* g) {
    asm volatile("cp.async.cg.shared.global [%0], [%1], 16;\n" :: "r"(s), "l"(g));
}
#define CP_COMMIT() asm volatile("cp.async.commit_group;\n" ::: "memory")
#define CP_WAIT0()  asm volatile("cp.async.wait_group 0;\n"  ::: "memory")
#define CP_WAIT1()  asm volatile("cp.async.wait_group 1;\n"  ::: "memory")

__device__ __forceinline__ void ldsm4(uint32_t& r0, uint32_t& r1, uint32_t& r2,
                                      uint32_t& r3, uint32_t addr) {
    asm volatile("ldmatrix.sync.aligned.m8n8.x4.shared.b16 {%0,%1,%2,%3}, [%4];"
                 : "=r"(r0), "=r"(r1), "=r"(r2), "=r"(r3) : "r"(addr));
}

// 64x64 fp32 tile, 256B rows, SW128 per 128B atom
__device__ __forceinline__ uint32_t tadr(int r, int c) {
    return (uint32_t)(r * 256 + ((c >> 3) << 7) + ((((c & 7) ^ (r & 7))) << 4));
}

// ---------------------------------------------------------------------------
// Batched tf32 rounding: grid.z selects tensor
// ---------------------------------------------------------------------------
__global__ void __launch_bounds__(256)
round_act3(const float4* __restrict__ i0, const float4* __restrict__ i1,
           const float4* __restrict__ i2, float4* __restrict__ o0,
           float4* __restrict__ o1, float4* __restrict__ o2)
{
    const float4* in;
    float4* out;
    if (blockIdx.z == 0)      { in = i0; out = o0; }
    else if (blockIdx.z == 1) { in = i1; out = o1; }
    else                      { in = i2; out = o2; }
    int i = blockIdx.x * 256 + threadIdx.x;
    float4 v = in[i];
    v.x = tf32r(v.x); v.y = tf32r(v.y); v.z = tf32r(v.z); v.w = tf32r(v.w);
    out[i] = v;
}

__global__ void __launch_bounds__(256)
round_w4(const float4* __restrict__ i0, const float4* __restrict__ i1,
         const float4* __restrict__ i2, const float4* __restrict__ i3,
         float4* __restrict__ o0, float4* __restrict__ o1,
         float4* __restrict__ o2, float4* __restrict__ o3)
{
    const float4* in;
    float4* out;
    if (blockIdx.z == 0)      { in = i0; out = o0; }
    else if (blockIdx.z == 1) { in = i1; out = o1; }
    else if (blockIdx.z == 2) { in = i2; out = o2; }
    else                      { in = i3; out = o3; }
    int i = blockIdx.x * 256 + threadIdx.x;
    float4 v = in[i];
    v.x = tf32r(v.x); v.y = tf32r(v.y); v.z = tf32r(v.z); v.w = tf32r(v.w);
    out[i] = v;
}

// ---------------------------------------------------------------------------
// V transpose: g_V [b*SEQ+s][e] -> g_VT [b*EMB+e][s]   (tiled 32x32)
// ---------------------------------------------------------------------------
__global__ void __launch_bounds__(256)
transpose_v(const float* __restrict__ V, float* __restrict__ VT)
{
    __shared__ float ts[32][33];
    const int s0 = blockIdx.x * 32;
    const int d0 = blockIdx.y * 32;
    const int b  = blockIdx.z;
    const int tx = threadIdx.x & 31;
    const int ty = threadIdx.x >> 5;
#pragma unroll
    for (int i = ty; i < 32; i += 8)
        ts[i][tx] = V[(size_t)(b * SEQ + s0 + i) * EMB + d0 + tx];
    __syncthreads();
#pragma unroll
    for (int i = ty; i < 32; i += 8)
        VT[(size_t)(b * EMB + d0 + i) * SEQ + s0 + tx] = ts[tx][i];
}

// ---------------------------------------------------------------------------
// GEMM core (single-barrier mainloop). C = A @ W^T + bias, tf32 inputs.
// ---------------------------------------------------------------------------
#define STAGE_BYTES 32768
#define GEMM_SMEM   (3 * STAGE_BYTES)

__device__ __forceinline__ void
gemm_body(const float* __restrict__ A, const float* __restrict__ Bw,
          const float* __restrict__ bias, float* __restrict__ C, int roundOut,
          char* dynsmem)
{
    const uint32_t smemBase = (uint32_t)__cvta_generic_to_shared(dynsmem);

    const int tid  = threadIdx.x;
    const int lane = tid & 31;
    const int warp = tid >> 5;
    const int wm   = warp & 1;
    const int wn   = warp >> 1;
    const int rowBlk = blockIdx.y * 128;
    const int colBlk = blockIdx.x * 128;

    int crow[4]; uint32_t csw[4];
#pragma unroll
    for (int i = 0; i < 4; i++) {
        int cid = tid + i * 256;
        int r   = cid >> 3;
        int cc  = cid & 7;
        crow[i] = r;
        csw[i]  = r * 128 + ((cc ^ (r & 7)) << 4);
    }

    float acc[4][4][4];
#pragma unroll
    for (int mi = 0; mi < 4; mi++)
#pragma unroll
        for (int ni = 0; ni < 4; ni++)
#pragma unroll
            for (int q = 0; q < 4; q++) acc[mi][ni][q] = 0.f;

    const int aRowL = (lane & 15);
    const int aChL  = (lane >> 4);
    const int bRowL = ((lane >> 4) << 3) + (lane & 7);
    const int bChL  = ((lane >> 3) & 1);

    auto issue = [&](int ks, int stage) {
        uint32_t sA = smemBase + stage * STAGE_BYTES;
        uint32_t sB = sA + 16384;
        const float* Ag = A  + (size_t)rowBlk * EMB + ks * 32;
        const float* Bg = Bw + (size_t)colBlk * EMB + ks * 32;
#pragma unroll
        for (int i = 0; i < 4; i++) {
            int cc = (tid + i * 256) & 7;
            cpa16(sA + csw[i], Ag + (size_t)crow[i] * EMB + cc * 4);
            cpa16(sB + csw[i], Bg + (size_t)crow[i] * EMB + cc * 4);
        }
    };

    issue(0, 0); CP_COMMIT();
    issue(1, 1); CP_COMMIT();

#pragma unroll 1
    for (int ks = 0; ks < NKS; ks++) {
        CP_WAIT1();                 // stage ks landed (per-thread)
        __syncthreads();            // visible to all; prior stage fully consumed

        uint32_t sA = smemBase + (ks % 3) * STAGE_BYTES;
        uint32_t sB = sA + 16384;

#pragma unroll
        for (int kt = 0; kt < 4; kt++) {
            uint32_t af[4][4];
            uint32_t bf[4][2];
#pragma unroll
            for (int mt = 0; mt < 4; mt++) {
                int r  = wm * 64 + mt * 16 + aRowL;
                int ch = 2 * kt + aChL;
                uint32_t addr = sA + r * 128 + ((ch ^ (r & 7)) << 4);
                ldsm4(af[mt][0], af[mt][1], af[mt][2], af[mt][3], addr);
            }
#pragma unroll
            for (int p = 0; p < 2; p++) {
                int r  = wn * 32 + p * 16 + bRowL;
                int ch = 2 * kt + bChL;
                uint32_t addr = sB + r * 128 + ((ch ^ (r & 7)) << 4);
                uint32_t t0, t1, t2, t3;
                ldsm4(t0, t1, t2, t3, addr);
                bf[2 * p][0] = t0; bf[2 * p][1] = t1;
                bf[2 * p + 1][0] = t2; bf[2 * p + 1][1] = t3;
            }
#pragma unroll
            for (int mi = 0; mi < 4; mi++)
#pragma unroll
                for (int ni = 0; ni < 4; ni++)
                    mma8(acc[mi][ni], af[mi], bf[ni]);
        }

        if (ks + 2 < NKS) issue(ks + 2, (ks + 2) % 3);
        CP_COMMIT();
    }

    const int g  = lane >> 2;
    const int tg = lane & 3;
#pragma unroll
    for (int mi = 0; mi < 4; mi++) {
        int r0 = rowBlk + wm * 64 + mi * 16 + g;
#pragma unroll
        for (int ni = 0; ni < 4; ni++) {
            int c0 = colBlk + wn * 32 + ni * 8 + tg * 2;
            float2 bb = *(const float2*)&bias[c0];
            float2 s0 = make_float2(acc[mi][ni][0] + bb.x, acc[mi][ni][1] + bb.y);
            float2 s1 = make_float2(acc[mi][ni][2] + bb.x, acc[mi][ni][3] + bb.y);
            if (roundOut) {
                s0.x = tf32r(s0.x); s0.y = tf32r(s0.y);
                s1.x = tf32r(s1.x); s1.y = tf32r(s1.y);
            }
            *(float2*)&C[(size_t)r0 * EMB + c0]       = s0;
            *(float2*)&C[(size_t)(r0 + 8) * EMB + c0] = s1;
        }
    }
}

// Merged QKV projection: grid.z = 0/1/2 selects (A, W, bias, C).
__global__ void __launch_bounds__(256)
gemm_qkv(const float* A0, const float* A1, const float* A2,
         const float* W0, const float* W1, const float* W2,
         const float* b0, const float* b1, const float* b2,
         float* C0, float* C1, float* C2)
{
    extern __shared__ __align__(128) char dynsmem[];
    const float *A, *W, *bi;
    float* C;
    if (blockIdx.z == 0)      { A = A0; W = W0; bi = b0; C = C0; }
    else if (blockIdx.z == 1) { A = A1; W = W1; bi = b1; C = C1; }
    else                      { A = A2; W = W2; bi = b2; C = C2; }
    gemm_body(A, W, bi, C, 1, dynsmem);
}

// Single GEMM (O projection)
__global__ void __launch_bounds__(256)
gemm_single(const float* __restrict__ A, const float* __restrict__ W,
            const float* __restrict__ bias, float* __restrict__ C, int roundOut)
{
    extern __shared__ __align__(128) char dynsmem[];
    gemm_body(A, W, bias, C, roundOut, dynsmem);
}

// ---------------------------------------------------------------------------
// MMA flash attention (R8-proven) with reversed CTA order for LPT scheduling:
// heavy (long-history) query tiles launch first.
// ---------------------------------------------------------------------------
#define ATT_SMEM (5 * 16384)

__global__ void __launch_bounds__(128)
attn_mma_kernel(const float* __restrict__ Q, const float* __restrict__ K,
                const float* __restrict__ VT, float* __restrict__ O)
{
    extern __shared__ __align__(128) char asmem[];
    const uint32_t base = (uint32_t)__cvta_generic_to_shared(asmem);
    const uint32_t Pb = base;

    const int tid  = threadIdx.x;
    const int lane = tid & 31;
    const int warp = tid >> 5;
    const int bh = blockIdx.y;
    const int b  = bh >> 4;
    const int h  = bh & 15;
    const int qTile = gridDim.x - 1 - blockIdx.x;   // heavy tiles first
    const int qBase = qTile * 64;
    const int nT = qTile + 1;

    const int g  = lane >> 2;
    const int tg = lane & 3;
    const int aRowL = lane & 15;
    const int aChL  = lane >> 4;
    const int bRowL = ((lane >> 4) << 3) + (lane & 7);
    const int bChL  = ((lane >> 3) & 1);

    // ---- stage Q tile into P region, preload A-fragments ----
    {
        const float* Qg = Q + ((size_t)(b * SEQ + qBase)) * EMB + h * HDIM;
#pragma unroll
        for (int i = 0; i < 8; i++) {
            int f = tid + i * 128;
            int r = f >> 4, c = f & 15;
            cpa16(Pb + tadr(r, c), Qg + (size_t)r * EMB + c * 4);
        }
    }
    CP_COMMIT(); CP_WAIT0();
    __syncthreads();

    uint32_t qf[8][4];
#pragma unroll
    for (int kt = 0; kt < 8; kt++) {
        int r = warp * 16 + aRowL;
        ldsm4(qf[kt][0], qf[kt][1], qf[kt][2], qf[kt][3],
              Pb + tadr(r, 2 * kt + aChL));
    }
    __syncthreads();

    float oacc[8][4];
#pragma unroll
    for (int n = 0; n < 8; n++)
#pragma unroll
        for (int q = 0; q < 4; q++) oacc[n][q] = 0.f;
    float m0 = -1e30f, m1 = -1e30f, l0 = 0.f, l1 = 0.f;

    auto prefetch = [&](int t) {
        uint32_t Kb = base + 16384 + (t & 1) * 16384;
        uint32_t Vb = base + 49152 + (t & 1) * 16384;
        const float* Kg = K  + ((size_t)(b * SEQ + t * 64)) * EMB + h * HDIM;
        const float* Vg = VT + ((size_t)(b * EMB + h * HDIM)) * SEQ + t * 64;
#pragma unroll
        for (int i = 0; i < 8; i++) {
            int f = tid + i * 128;
            int r = f >> 4, c = f & 15;
            cpa16(Kb + tadr(r, c), Kg + (size_t)r * EMB + c * 4);
            cpa16(Vb + tadr(r, c), Vg + (size_t)r * SEQ + c * 4);
        }
    };

    prefetch(0); CP_COMMIT();
    if (nT > 1) prefetch(1);
    CP_COMMIT();

#pragma unroll 1
    for (int t = 0; t < nT; t++) {
        CP_WAIT1();
        __syncthreads();

        const uint32_t Kb = base + 16384 + (t & 1) * 16384;
        const uint32_t Vb = base + 49152 + (t & 1) * 16384;

        // ---- S = Q @ K^T ----
        float sacc[8][4];
#pragma unroll
        for (int n = 0; n < 8; n++)
#pragma unroll
            for (int q = 0; q < 4; q++) sacc[n][q] = 0.f;

#pragma unroll
        for (int kt = 0; kt < 8; kt++) {
            uint32_t bf[8][2];
#pragma unroll
            for (int p = 0; p < 4; p++) {
                int r = p * 16 + bRowL;
                uint32_t t0, t1, t2, t3;
                ldsm4(t0, t1, t2, t3, Kb + tadr(r, 2 * kt + bChL));
                bf[2 * p][0] = t0;     bf[2 * p][1] = t1;
                bf[2 * p + 1][0] = t2; bf[2 * p + 1][1] = t3;
            }
#pragma unroll
            for (int n = 0; n < 8; n++)
                mma8(sacc[n], qf[kt], bf[n]);
        }

#pragma unroll
        for (int n = 0; n < 8; n++)
#pragma unroll
            for (int q = 0; q < 4; q++) sacc[n][q] *= ATTN_SCALE;

        if (t == qTile) {
            int r0 = warp * 16 + g;
            int r1 = r0 + 8;
#pragma unroll
            for (int n = 0; n < 8; n++) {
                int c0 = n * 8 + tg * 2;
                int c1 = c0 + 1;
                if (c0 > r0) sacc[n][0] = -1e30f;
                if (c1 > r0) sacc[n][1] = -1e30f;
                if (c0 > r1) sacc[n][2] = -1e30f;
                if (c1 > r1) sacc[n][3] = -1e30f;
            }
        }

        // ---- online softmax ----
        float tm0 = -1e30f, tm1 = -1e30f;
#pragma unroll
        for (int n = 0; n < 8; n++) {
            tm0 = fmaxf(tm0, fmaxf(sacc[n][0], sacc[n][1]));
            tm1 = fmaxf(tm1, fmaxf(sacc[n][2], sacc[n][3]));
        }
        tm0 = fmaxf(tm0, __shfl_xor_sync(0xFFFFFFFFu, tm0, 1));
        tm0 = fmaxf(tm0, __shfl_xor_sync(0xFFFFFFFFu, tm0, 2));
        tm1 = fmaxf(tm1, __shfl_xor_sync(0xFFFFFFFFu, tm1, 1));
        tm1 = fmaxf(tm1, __shfl_xor_sync(0xFFFFFFFFu, tm1, 2));

        float nm0 = fmaxf(m0, tm0);
        float nm1 = fmaxf(m1, tm1);
        float cr0 = __expf(m0 - nm0);
        float cr1 = __expf(m1 - nm1);
        m0 = nm0; m1 = nm1;

        float rs0 = 0.f, rs1 = 0.f;
#pragma unroll
        for (int n = 0; n < 8; n++) {
            float p0 = tf32r(__expf(sacc[n][0] - nm0));
            float p1 = tf32r(__expf(sacc[n][1] - nm0));
            float p2 = tf32r(__expf(sacc[n][2] - nm1));
            float p3 = tf32r(__expf(sacc[n][3] - nm1));
            sacc[n][0] = p0; sacc[n][1] = p1; sacc[n][2] = p2; sacc[n][3] = p3;
            rs0 += p0 + p1; rs1 += p2 + p3;
        }
        rs0 += __shfl_xor_sync(0xFFFFFFFFu, rs0, 1);
        rs0 += __shfl_xor_sync(0xFFFFFFFFu, rs0, 2);
        rs1 += __shfl_xor_sync(0xFFFFFFFFu, rs1, 1);
        rs1 += __shfl_xor_sync(0xFFFFFFFFu, rs1, 2);
        l0 = l0 * cr0 + rs0;
        l1 = l1 * cr1 + rs1;

#pragma unroll
        for (int n = 0; n < 8; n++) {
            oacc[n][0] *= cr0; oacc[n][1] *= cr0;
            oacc[n][2] *= cr1; oacc[n][3] *= cr1;
        }

        // ---- P -> SMEM (warp-private rows) ----
        {
            int r0 = warp * 16 + g;
#pragma unroll
            for (int n = 0; n < 8; n++) {
                int off = n * 8 + tg * 2;
                int ch  = off >> 2;
                int byo = (off & 3) * 4;
                *(float2*)(asmem + tadr(r0, ch) + byo)     = make_float2(sacc[n][0], sacc[n][1]);
                *(float2*)(asmem + tadr(r0 + 8, ch) + byo) = make_float2(sacc[n][2], sacc[n][3]);
            }
        }
        __syncwarp();

        // ---- O += P @ V ----
#pragma unroll
        for (int kt = 0; kt < 8; kt++) {
            uint32_t pa[4];
            {
                int r = warp * 16 + aRowL;
                ldsm4(pa[0], pa[1], pa[2], pa[3], Pb + tadr(r, 2 * kt + aChL));
            }
            uint32_t vf[8][2];
#pragma unroll
            for (int p = 0; p < 4; p++) {
                int r = p * 16 + bRowL;
                uint32_t t0, t1, t2, t3;
                ldsm4(t0, t1, t2, t3, Vb + tadr(r, 2 * kt + bChL));
                vf[2 * p][0] = t0;     vf[2 * p][1] = t1;
                vf[2 * p + 1][0] = t2; vf[2 * p + 1][1] = t3;
            }
#pragma unroll
            for (int n = 0; n < 8; n++)
                mma8(oacc[n], pa, vf[n]);
        }

        __syncthreads();
        if (t + 2 < nT) prefetch(t + 2);
        CP_COMMIT();
    }

    const float iv0 = 1.f / l0;
    const float iv1 = 1.f / l1;
    const int row0 = qBase + warp * 16 + g;
    const int row1 = row0 + 8;
    float* O0 = O + ((size_t)(b * SEQ + row0)) * EMB + h * HDIM;
    float* O1 = O + ((size_t)(b * SEQ + row1)) * EMB + h * HDIM;
#pragma unroll
    for (int n = 0; n < 8; n++) {
        int c = n * 8 + tg * 2;
        *(float2*)&O0[c] = make_float2(tf32r(oacc[n][0] * iv0), tf32r(oacc[n][1] * iv0));
        *(float2*)&O1[c] = make_float2(tf32r(oacc[n][2] * iv1), tf32r(oacc[n][3] * iv1));
    }
}

// ---------------------------------------------------------------------------
// Launch
// ---------------------------------------------------------------------------
extern "C" void kernel_launch(void* const* d_in, const int* in_sizes, int n_in,
                              void* d_out, int out_size)
{
    const float* xq = (const float*)d_in[0];
    const float* xk = (const float*)d_in[1];
    const float* xv = (const float*)d_in[2];
    // d_in[3] = mask (deterministic causal tril) — exploited structurally
    const float* Wq = (const float*)d_in[4];
    const float* bq = (const float*)d_in[5];
    const float* Wk = (const float*)d_in[6];
    const float* bk = (const float*)d_in[7];
    const float* Wv = (const float*)d_in[8];
    const float* bv = (const float*)d_in[9];
    const float* Wo = (const float*)d_in[10];
    const float* bo = (const float*)d_in[11];
    float* out = (float*)d_out;

    float *pQ, *pK, *pV, *pA, *pVT;
    float *pRX0, *pRX1, *pRX2, *pRW0, *pRW1, *pRW2, *pRW3;
    cudaGetSymbolAddress((void**)&pQ,   g_Q);
    cudaGetSymbolAddress((void**)&pK,   g_K);
    cudaGetSymbolAddress((void**)&pV,   g_V);
    cudaGetSymbolAddress((void**)&pA,   g_A);
    cudaGetSymbolAddress((void**)&pVT,  g_VT);
    cudaGetSymbolAddress((void**)&pRX0, g_RX0);
    cudaGetSymbolAddress((void**)&pRX1, g_RX1);
    cudaGetSymbolAddress((void**)&pRX2, g_RX2);
    cudaGetSymbolAddress((void**)&pRW0, g_RW0);
    cudaGetSymbolAddress((void**)&pRW1, g_RW1);
    cudaGetSymbolAddress((void**)&pRW2, g_RW2);
    cudaGetSymbolAddress((void**)&pRW3, g_RW3);

    cudaFuncSetAttribute(gemm_qkv,
                         cudaFuncAttributeMaxDynamicSharedMemorySize, GEMM_SMEM);
    cudaFuncSetAttribute(gemm_single,
                         cudaFuncAttributeMaxDynamicSharedMemorySize, GEMM_SMEM);
    cudaFuncSetAttribute(attn_mma_kernel,
                         cudaFuncAttributeMaxDynamicSharedMemorySize, ATT_SMEM);

    // ---- rounding: 2 launches ----
    const int rXblocks = (MROWS * EMB / 4) / 256;  // 4096
    const int rWblocks = (EMB * EMB / 4) / 256;    // 1024
    round_act3<<<dim3(rXblocks, 1, 3), 256>>>(
        (const float4*)xq, (const float4*)xk, (const float4*)xv,
        (float4*)pRX0, (float4*)pRX1, (float4*)pRX2);
    round_w4<<<dim3(rWblocks, 1, 4), 256>>>(
        (const float4*)Wq, (const float4*)Wk, (const float4*)Wv, (const float4*)Wo,
        (float4*)pRW0, (float4*)pRW1, (float4*)pRW2, (float4*)pRW3);

    // ---- QKV projections, one launch ----
    dim3 ggrid(EMB / 128, MROWS / 128, 3);   // (8, 32, 3) = 768 CTAs
    gemm_qkv<<<ggrid, 256, GEMM_SMEM>>>(pRX0, pRX1, pRX2,
                                        pRW0, pRW1, pRW2,
                                        bq, bk, bv,
                                        pQ, pK, pV);

    // ---- V transpose ----
    transpose_v<<<dim3(SEQ / 32, EMB / 32, BATCH), 256>>>(pV, pVT);

    // ---- MMA flash attention ----
    attn_mma_kernel<<<dim3(SEQ / 64, BATCH * NHEAD), 128, ATT_SMEM>>>(pQ, pK, pVT, pA);

    // ---- O projection ----
    gemm_single<<<dim3(EMB / 128, MROWS / 128), 256, GEMM_SMEM>>>(pA, pRW3, bo, out, 0);
}